// round 4
// baseline (speedup 1.0000x reference)
#include <cuda_runtime.h>
#include <math.h>

// ---------------- Problem-size constants ----------------
#define NMAX 100000
#define EMAX 1600000

// ---------------- Device scratch (no allocations allowed) ----------------
__device__ int   g_deg_out[NMAX];
__device__ int   g_deg_in[NMAX];
__device__ float g_norm_s[NMAX];
__device__ float g_norm_d[NMAX];
__device__ int   g_row_ptr[NMAX + 1];
__device__ int   g_cursor[NMAX];
__device__ int   g_csr_src[EMAX];
__device__ float g_H[(size_t)NMAX * 256];   // fused [Xw*norm_s | Xres] per layer
__device__ float g_X[(size_t)NMAX * 128];   // hidden activations

// ---------------- Setup kernels ----------------
__global__ void gres_zero_deg(int n) {
    int i = blockIdx.x * blockDim.x + threadIdx.x;
    if (i < n) { g_deg_out[i] = 0; g_deg_in[i] = 0; }
}

__global__ void gres_degrees(const int* __restrict__ src, const int* __restrict__ dst, int E) {
    int i = blockIdx.x * blockDim.x + threadIdx.x;
    if (i < E) {
        atomicAdd(&g_deg_out[src[i]], 1);
        atomicAdd(&g_deg_in[dst[i]], 1);
    }
}

__global__ void gres_norms(int n) {
    int i = blockIdx.x * blockDim.x + threadIdx.x;
    if (i < n) {
        g_norm_s[i] = rsqrtf(fmaxf((float)g_deg_out[i], 1.0f));
        g_norm_d[i] = rsqrtf(fmaxf((float)g_deg_in[i], 1.0f));
    }
}

// Single-block exclusive scan of g_deg_in -> g_row_ptr / g_cursor
__global__ void gres_scan(int n) {
    __shared__ int sums[1024];
    int t = threadIdx.x;
    int chunk = (n + 1023) >> 10;
    int b = t * chunk;
    int e = min(b + chunk, n);
    int s = 0;
    for (int i = b; i < e; i++) s += g_deg_in[i];
    sums[t] = s;
    __syncthreads();
    for (int off = 1; off < 1024; off <<= 1) {
        int v = (t >= off) ? sums[t - off] : 0;
        __syncthreads();
        sums[t] += v;
        __syncthreads();
    }
    int prefix = (t > 0) ? sums[t - 1] : 0;
    for (int i = b; i < e; i++) {
        g_row_ptr[i] = prefix;
        g_cursor[i]  = prefix;
        prefix += g_deg_in[i];
    }
    if (t == 0) g_row_ptr[n] = sums[1023];
}

__global__ void gres_scatter(const int* __restrict__ src, const int* __restrict__ dst, int E) {
    int i = blockIdx.x * blockDim.x + threadIdx.x;
    if (i < E) {
        int p = atomicAdd(&g_cursor[dst[i]], 1);
        g_csr_src[p] = src[i];
    }
}

// ---------------- Fused GEMM: H[:, :Kw] = (X @ W) * norm_s ; H[:, Kw:] = X @ R ----------------
// K = 128 fixed. BM=64, BN=64, BK=32, 256 threads, 4x4 register tile.
// grid.x = ceil(n/64), grid.y = 2*Kw/64. Column blocks are entirely in W or entirely in R.
__global__ void gres_gemm(const float* __restrict__ X, const float* __restrict__ W,
                          const float* __restrict__ R, int n, int Kw) {
    __shared__ __align__(16) float As[64][33];
    __shared__ __align__(16) float Bs[32][64];

    int tid = threadIdx.x;
    int rowBase = blockIdx.x * 64;
    int colBase = blockIdx.y * 64;
    int Nw = 2 * Kw;
    bool isW = (colBase < Kw);
    const float* B = isW ? (W + colBase) : (R + (colBase - Kw));

    int tr = (tid >> 4) * 4;   // thread row offset in tile (0..60)
    int tc = (tid & 15) * 4;   // thread col offset in tile (0..60)

    float acc[4][4];
#pragma unroll
    for (int i = 0; i < 4; i++)
#pragma unroll
        for (int j = 0; j < 4; j++) acc[i][j] = 0.0f;

    for (int kt = 0; kt < 4; kt++) {
        // load A tile: 64 rows x 32 cols (512 float4, 2 per thread)
#pragma unroll
        for (int j = 0; j < 2; j++) {
            int i4 = tid + 256 * j;
            int r = i4 >> 3;
            int k = (i4 & 7) * 4;
            int gr = rowBase + r;
            float4 v = make_float4(0.f, 0.f, 0.f, 0.f);
            if (gr < n) v = *(const float4*)(X + (size_t)gr * 128 + kt * 32 + k);
            As[r][k + 0] = v.x; As[r][k + 1] = v.y; As[r][k + 2] = v.z; As[r][k + 3] = v.w;
        }
        // load B tile: 32 rows x 64 cols (512 float4, 2 per thread)
#pragma unroll
        for (int j = 0; j < 2; j++) {
            int i4 = tid + 256 * j;
            int k = i4 >> 4;
            int c = (i4 & 15) * 4;
            float4 v = *(const float4*)(B + (size_t)(kt * 32 + k) * Kw + c);
            *(float4*)&Bs[k][c] = v;
        }
        __syncthreads();

#pragma unroll
        for (int k = 0; k < 32; k++) {
            float a[4], b[4];
#pragma unroll
            for (int i = 0; i < 4; i++) a[i] = As[tr + i][k];
#pragma unroll
            for (int j = 0; j < 4; j++) b[j] = Bs[k][tc + j];
#pragma unroll
            for (int i = 0; i < 4; i++)
#pragma unroll
                for (int j = 0; j < 4; j++) acc[i][j] = fmaf(a[i], b[j], acc[i][j]);
        }
        __syncthreads();
    }

#pragma unroll
    for (int i = 0; i < 4; i++) {
        int gr = rowBase + tr + i;
        if (gr >= n) continue;
        float sc = isW ? g_norm_s[gr] : 1.0f;
        float4 o;
        o.x = acc[i][0] * sc; o.y = acc[i][1] * sc;
        o.z = acc[i][2] * sc; o.w = acc[i][3] * sc;
        *(float4*)(g_H + (size_t)gr * Nw + colBase + tc) = o;
    }
}

// ---------------- Fused SpMM + combine, Kw=128 (H width 256) ----------------
// One warp per dst row. lane holds gc floats [lane*4..+3] and res floats [128+lane*4..+3].
// out[row] = relu( S_gc * norm_d[row] + S_res + bias )
__global__ void gres_spmm128(const float* __restrict__ bias, float* __restrict__ out, int n,
                             int do_relu) {
    int warp = (blockIdx.x * blockDim.x + threadIdx.x) >> 5;
    if (warp >= n) return;
    int lane = threadIdx.x & 31;
    int row = warp;

    int s0 = g_row_ptr[row];
    int s1 = g_row_ptr[row + 1];

    float4 a0 = make_float4(0.f, 0.f, 0.f, 0.f);
    float4 a1 = make_float4(0.f, 0.f, 0.f, 0.f);

    int j = s0;
    for (; j + 1 < s1; j += 2) {
        int sa = g_csr_src[j];
        int sb = g_csr_src[j + 1];
        const float4* ha = (const float4*)(g_H + (size_t)sa * 256);
        const float4* hb = (const float4*)(g_H + (size_t)sb * 256);
        float4 v0a = ha[lane], v1a = ha[lane + 32];
        float4 v0b = hb[lane], v1b = hb[lane + 32];
        a0.x += v0a.x + v0b.x; a0.y += v0a.y + v0b.y;
        a0.z += v0a.z + v0b.z; a0.w += v0a.w + v0b.w;
        a1.x += v1a.x + v1b.x; a1.y += v1a.y + v1b.y;
        a1.z += v1a.z + v1b.z; a1.w += v1a.w + v1b.w;
    }
    if (j < s1) {
        int sa = g_csr_src[j];
        const float4* ha = (const float4*)(g_H + (size_t)sa * 256);
        float4 v0a = ha[lane], v1a = ha[lane + 32];
        a0.x += v0a.x; a0.y += v0a.y; a0.z += v0a.z; a0.w += v0a.w;
        a1.x += v1a.x; a1.y += v1a.y; a1.z += v1a.z; a1.w += v1a.w;
    }

    float nd = g_norm_d[row];
    float4 b4 = *(const float4*)(bias + lane * 4);
    float4 o;
    o.x = fmaf(a0.x, nd, a1.x + b4.x);
    o.y = fmaf(a0.y, nd, a1.y + b4.y);
    o.z = fmaf(a0.z, nd, a1.z + b4.z);
    o.w = fmaf(a0.w, nd, a1.w + b4.w);
    if (do_relu) {
        o.x = fmaxf(o.x, 0.f); o.y = fmaxf(o.y, 0.f);
        o.z = fmaxf(o.z, 0.f); o.w = fmaxf(o.w, 0.f);
    }
    *(float4*)(out + (size_t)row * 128 + lane * 4) = o;
}

// ---------------- Fused SpMM + combine, Kw=64 (H width 128), no relu ----------------
// lane<16 holds gc cols [lane*4], lane>=16 holds res cols [(lane-16)*4]; shuffle to combine.
__global__ void gres_spmm64(const float* __restrict__ bias, float* __restrict__ out, int n) {
    int warp = (blockIdx.x * blockDim.x + threadIdx.x) >> 5;
    if (warp >= n) return;
    int lane = threadIdx.x & 31;
    int row = warp;

    int s0 = g_row_ptr[row];
    int s1 = g_row_ptr[row + 1];

    float4 a0 = make_float4(0.f, 0.f, 0.f, 0.f);

    int j = s0;
    for (; j + 1 < s1; j += 2) {
        int sa = g_csr_src[j];
        int sb = g_csr_src[j + 1];
        const float4* ha = (const float4*)(g_H + (size_t)sa * 128);
        const float4* hb = (const float4*)(g_H + (size_t)sb * 128);
        float4 va = ha[lane], vb = hb[lane];
        a0.x += va.x + vb.x; a0.y += va.y + vb.y;
        a0.z += va.z + vb.z; a0.w += va.w + vb.w;
    }
    if (j < s1) {
        int sa = g_csr_src[j];
        const float4* ha = (const float4*)(g_H + (size_t)sa * 128);
        float4 va = ha[lane];
        a0.x += va.x; a0.y += va.y; a0.z += va.z; a0.w += va.w;
    }

    // bring res partial (lanes 16..31) over to gc lanes (0..15)
    float ox = __shfl_xor_sync(0xffffffffu, a0.x, 16);
    float oy = __shfl_xor_sync(0xffffffffu, a0.y, 16);
    float oz = __shfl_xor_sync(0xffffffffu, a0.z, 16);
    float ow = __shfl_xor_sync(0xffffffffu, a0.w, 16);

    if (lane < 16) {
        float nd = g_norm_d[row];
        float4 b4 = *(const float4*)(bias + lane * 4);
        float4 o;
        o.x = fmaf(a0.x, nd, ox + b4.x);
        o.y = fmaf(a0.y, nd, oy + b4.y);
        o.z = fmaf(a0.z, nd, oz + b4.z);
        o.w = fmaf(a0.w, nd, ow + b4.w);
        *(float4*)(out + (size_t)row * 64 + lane * 4) = o;
    }
}

// ---------------- Host launch ----------------
extern "C" void kernel_launch(void* const* d_in, const int* in_sizes, int n_in,
                              void* d_out, int out_size) {
    const float* raw_x = (const float*)d_in[0];
    const int*   src   = (const int*)d_in[1];
    const int*   dst   = (const int*)d_in[2];
    const float* gw0   = (const float*)d_in[3];
    const float* gb0   = (const float*)d_in[4];
    const float* gw1   = (const float*)d_in[5];
    const float* gb1   = (const float*)d_in[6];
    const float* gw2   = (const float*)d_in[7];
    const float* gb2   = (const float*)d_in[8];
    const float* rw0   = (const float*)d_in[9];
    const float* rw1   = (const float*)d_in[10];
    const float* rw2   = (const float*)d_in[11];
    float* out = (float*)d_out;

    int n = in_sizes[0] / 128;
    int E = in_sizes[1];

    float* Xp = nullptr;
    cudaGetSymbolAddress((void**)&Xp, g_X);

    // graph setup
    gres_zero_deg<<<(n + 255) / 256, 256>>>(n);
    gres_degrees<<<(E + 255) / 256, 256>>>(src, dst, E);
    gres_norms<<<(n + 255) / 256, 256>>>(n);
    gres_scan<<<1, 1024>>>(n);
    gres_scatter<<<(E + 255) / 256, 256>>>(src, dst, E);

    int spmm_blocks = (n + 7) / 8;  // 8 warps per 256-thread block

    // layer 0: X=raw_x, Kw=128
    {
        dim3 grid((n + 63) / 64, 4);
        gres_gemm<<<grid, 256>>>(raw_x, gw0, rw0, n, 128);
        gres_spmm128<<<spmm_blocks, 256>>>(gb0, Xp, n, 1);
    }
    // layer 1: X=g_X, Kw=128
    {
        dim3 grid((n + 63) / 64, 4);
        gres_gemm<<<grid, 256>>>(Xp, gw1, rw1, n, 128);
        gres_spmm128<<<spmm_blocks, 256>>>(gb1, Xp, n, 1);
    }
    // layer 2: X=g_X, Kw=64, no relu, writes d_out
    {
        dim3 grid((n + 63) / 64, 2);
        gres_gemm<<<grid, 256>>>(Xp, gw2, rw2, n, 64);
        gres_spmm64<<<spmm_blocks, 256>>>(gb2, out, n);
    }
}

// round 7
// speedup vs baseline: 1.5595x; 1.5595x over previous
#include <cuda_runtime.h>
#include <cuda_bf16.h>
#include <math.h>
#include <stdint.h>

// ---------------- Problem-size constants ----------------
#define NMAX 100000
#define EMAX 1600000

// ---------------- Device scratch ----------------
__device__ int   g_deg_out[NMAX];
__device__ int   g_deg_in[NMAX];
__device__ float g_norm_s[NMAX];
__device__ float g_norm_d[NMAX];
__device__ int   g_row_ptr[NMAX + 1];
__device__ int   g_cursor[NMAX];
__device__ int   g_csr_src[EMAX];
__device__ float g_H[(size_t)NMAX * 256];   // fused [Xw*norm_s | Xres] per layer
__device__ float g_X[(size_t)NMAX * 128];   // hidden activations
__device__ int   g_blk[512];                // scan block sums
// Row-major bf16 images of fused B^T (hi / lo split): [Nw rows x 128 K], 256B/row
__device__ __align__(128) unsigned char g_Bhi[65536];
__device__ __align__(128) unsigned char g_Blo[65536];

// ---------------- Setup kernels ----------------
__global__ void gres_zero_deg(int n) {
    int i = blockIdx.x * blockDim.x + threadIdx.x;
    if (i < n) { g_deg_out[i] = 0; g_deg_in[i] = 0; }
}

__global__ void gres_degrees(const int* __restrict__ src, const int* __restrict__ dst, int E) {
    int i = blockIdx.x * blockDim.x + threadIdx.x;
    if (i < E) {
        atomicAdd(&g_deg_out[src[i]], 1);
        atomicAdd(&g_deg_in[dst[i]], 1);
    }
}

__global__ void gres_norms(int n) {
    int i = blockIdx.x * blockDim.x + threadIdx.x;
    if (i < n) {
        g_norm_s[i] = rsqrtf(fmaxf((float)g_deg_out[i], 1.0f));
        g_norm_d[i] = rsqrtf(fmaxf((float)g_deg_in[i], 1.0f));
    }
}

// 3-phase chip-wide exclusive scan of g_deg_in -> g_row_ptr / g_cursor
__global__ void gres_scan1(int n) {
    __shared__ int sh[256];
    int i = blockIdx.x * 256 + threadIdx.x;
    sh[threadIdx.x] = (i < n) ? g_deg_in[i] : 0;
    __syncthreads();
    for (int off = 128; off; off >>= 1) {
        if (threadIdx.x < off) sh[threadIdx.x] += sh[threadIdx.x + off];
        __syncthreads();
    }
    if (threadIdx.x == 0) g_blk[blockIdx.x] = sh[0];
}

__global__ void gres_scan2(int nb) {
    __shared__ int sh[512];
    int t = threadIdx.x;
    int v = (t < nb) ? g_blk[t] : 0;
    sh[t] = v;
    __syncthreads();
    for (int off = 1; off < 512; off <<= 1) {
        int u = (t >= off) ? sh[t - off] : 0;
        __syncthreads();
        sh[t] += u;
        __syncthreads();
    }
    g_blk[t] = sh[t] - v;  // exclusive
}

__global__ void gres_scan3(int n) {
    __shared__ int sh[256];
    int t = threadIdx.x;
    int i = blockIdx.x * 256 + t;
    int v = (i < n) ? g_deg_in[i] : 0;
    sh[t] = v;
    __syncthreads();
    for (int off = 1; off < 256; off <<= 1) {
        int u = (t >= off) ? sh[t - off] : 0;
        __syncthreads();
        sh[t] += u;
        __syncthreads();
    }
    int excl = sh[t] - v + g_blk[blockIdx.x];
    if (i < n) { g_row_ptr[i] = excl; g_cursor[i] = excl; }
    if (i == n - 1) g_row_ptr[n] = excl + v;
}

__global__ void gres_scatter(const int* __restrict__ src, const int* __restrict__ dst, int E) {
    int i = blockIdx.x * blockDim.x + threadIdx.x;
    if (i < E) {
        int p = atomicAdd(&g_cursor[dst[i]], 1);
        g_csr_src[p] = src[i];
    }
}

// ---------------- B prep: fused W^T split into row-major bf16 hi/lo images ----------------
// B[nr][k] = nr<Kw ? W[k][nr] : R[k][nr-Kw],  [Nw rows x 128 K]
__global__ void gres_prep_b(const float* __restrict__ W, const float* __restrict__ R, int Kw) {
    int Nw = 2 * Kw;
    int idx = blockIdx.x * blockDim.x + threadIdx.x;
    if (idx >= Nw * 128) return;
    int nr = idx >> 7;
    int k  = idx & 127;
    float v = (nr < Kw) ? W[(size_t)k * Kw + nr] : R[(size_t)k * Kw + (nr - Kw)];
    __nv_bfloat16 h = __float2bfloat16(v);
    __nv_bfloat16 l = __float2bfloat16(v - __bfloat162float(h));
    ((__nv_bfloat16*)g_Bhi)[idx] = h;
    ((__nv_bfloat16*)g_Blo)[idx] = l;
}

// ---------------- mma.sync helpers (baseline PTX, compiles on compute_103) ----------------
__device__ __forceinline__ uint32_t smem_u32(const void* p) {
    uint32_t a;
    asm("{ .reg .u64 t; cvta.to.shared.u64 t, %1; cvt.u32.u64 %0, t; }" : "=r"(a) : "l"(p));
    return a;
}

__device__ __forceinline__ void ldsm_x4(uint32_t& r0, uint32_t& r1, uint32_t& r2, uint32_t& r3,
                                        uint32_t addr) {
    asm volatile("ldmatrix.sync.aligned.m8n8.x4.shared.b16 {%0,%1,%2,%3}, [%4];"
                 : "=r"(r0), "=r"(r1), "=r"(r2), "=r"(r3) : "r"(addr));
}

__device__ __forceinline__ void mma_bf16(float& c0, float& c1, float& c2, float& c3,
                                         uint32_t a0, uint32_t a1, uint32_t a2, uint32_t a3,
                                         uint32_t b0, uint32_t b1) {
    asm volatile(
        "mma.sync.aligned.m16n8k16.row.col.f32.bf16.bf16.f32 "
        "{%0,%1,%2,%3}, {%4,%5,%6,%7}, {%8,%9}, {%0,%1,%2,%3};"
        : "+f"(c0), "+f"(c1), "+f"(c2), "+f"(c3)
        : "r"(a0), "r"(a1), "r"(a2), "r"(a3), "r"(b0), "r"(b1));
}

__device__ __forceinline__ uint32_t pack_bf16x2(float a, float b) {
    __nv_bfloat162 t = __floats2bfloat162_rn(a, b);
    return *(uint32_t*)&t;
}

// ---------------- Tensor-core GEMM (mma.sync bf16, hi/lo split) ----------------
// Per CTA: 128 M-rows x 128 N-cols, K=128. 256 threads = 8 warps (4m x 2n).
// D = Ahi*Bhi + Ahi*Blo + Alo*Bhi, fp32 accumulate.
// Epilogue: output col < Kw scaled by norm_s[row].
// SMEM layout (dynamic, 128KB): Ahi[32K] Alo[32K] Bhi[32K] Blo[32K].
// Tile layout: 128 rows x 256B (128 bf16); 16B chunk kc swizzled: kc ^ (row & 7).
#define SA_HI 0
#define SA_LO 32768
#define SB_HI 65536
#define SB_LO 98304

__global__ void __launch_bounds__(256, 1)
gres_gemm_mma(const float* __restrict__ X, int n, int Kw, float* __restrict__ Hout) {
    extern __shared__ __align__(1024) char sdyn[];
    uint32_t sbase = smem_u32(sdyn);

    int Nw = 2 * Kw;
    int tid = threadIdx.x;
    int lane = tid & 31, warp = tid >> 5;
    int rowBase = blockIdx.x * 128;
    int colBase = blockIdx.y * 128;

    // ---- load A tile: fp32 -> hi/lo bf16, swizzled smem ----
#pragma unroll
    for (int it = 0; it < 8; it++) {
        int id = tid + it * 256;          // 0..2047 chunk tasks
        int row = id >> 4;                // 0..127
        int kc  = id & 15;                // 16B chunk = 8 bf16 = 8 k-elems
        float4 v0 = make_float4(0.f, 0.f, 0.f, 0.f);
        float4 v1 = make_float4(0.f, 0.f, 0.f, 0.f);
        if (rowBase + row < n) {
            const float* xp = X + (size_t)(rowBase + row) * 128 + kc * 8;
            v0 = *(const float4*)xp;
            v1 = *(const float4*)(xp + 4);
        }
        uint4 hi, lo;
        hi.x = pack_bf16x2(v0.x, v0.y); hi.y = pack_bf16x2(v0.z, v0.w);
        hi.z = pack_bf16x2(v1.x, v1.y); hi.w = pack_bf16x2(v1.z, v1.w);
        // residual = v - bf16(v)
        __nv_bfloat162 h;
        float r0, r1;
        h = *(__nv_bfloat162*)&hi.x; r0 = v0.x - __bfloat162float(h.x); r1 = v0.y - __bfloat162float(h.y);
        lo.x = pack_bf16x2(r0, r1);
        h = *(__nv_bfloat162*)&hi.y; r0 = v0.z - __bfloat162float(h.x); r1 = v0.w - __bfloat162float(h.y);
        lo.y = pack_bf16x2(r0, r1);
        h = *(__nv_bfloat162*)&hi.z; r0 = v1.x - __bfloat162float(h.x); r1 = v1.y - __bfloat162float(h.y);
        lo.z = pack_bf16x2(r0, r1);
        h = *(__nv_bfloat162*)&hi.w; r0 = v1.z - __bfloat162float(h.x); r1 = v1.w - __bfloat162float(h.y);
        lo.w = pack_bf16x2(r0, r1);
        uint32_t off = row * 256 + ((kc ^ (row & 7)) << 4);
        *(uint4*)(sdyn + SA_HI + off) = hi;
        *(uint4*)(sdyn + SA_LO + off) = lo;
    }

    // ---- copy B images (row-major gmem) into swizzled smem ----
#pragma unroll
    for (int it = 0; it < 8; it++) {
        int id = tid + it * 256;
        int row = id >> 4;
        int kc  = id & 15;
        int srcIdx = (colBase + row) * 16 + kc;
        uint4 vh = ((const uint4*)g_Bhi)[srcIdx];
        uint4 vl = ((const uint4*)g_Blo)[srcIdx];
        uint32_t off = row * 256 + ((kc ^ (row & 7)) << 4);
        *(uint4*)(sdyn + SB_HI + off) = vh;
        *(uint4*)(sdyn + SB_LO + off) = vl;
    }
    __syncthreads();

    // ---- warp tiling: warp m-group (0..3) covers rows wm*32, n-group (0..1) covers cols wn*64 ----
    int wm = warp & 3, wn = warp >> 2;
    int lr = lane & 7, lg = lane >> 3;

    // Per-lane ldmatrix row assignments (fixed across ksteps)
    // A frags (mi=0,1): row = wm*32 + mi*16 + (lg&1)*8 + lr
    // B frags (ni=0..3): row = wn*64 + ni*16 + (lg&1)*8 + lr
    uint32_t aRow0 = wm * 32 + (lg & 1) * 8 + lr;
    uint32_t bRow0 = wn * 64 + (lg & 1) * 8 + lr;
    uint32_t kgrp = lg >> 1;  // 0 or 1: which k-chunk within the kstep

    float acc[2][8][4];
#pragma unroll
    for (int i = 0; i < 2; i++)
#pragma unroll
        for (int j = 0; j < 8; j++)
#pragma unroll
            for (int q = 0; q < 4; q++) acc[i][j][q] = 0.f;

#pragma unroll
    for (int s = 0; s < 3; s++) {
        uint32_t aB = sbase + ((s == 2) ? SA_LO : SA_HI);
        uint32_t bB = sbase + ((s == 1) ? SB_LO : SB_HI);
#pragma unroll
        for (int ks = 0; ks < 8; ks++) {
            uint32_t kc = ks * 2 + kgrp;
            uint32_t afr[2][4], bfr[4][4];
#pragma unroll
            for (int mi = 0; mi < 2; mi++) {
                uint32_t row = aRow0 + mi * 16;
                uint32_t addr = aB + row * 256 + (((kc) ^ (row & 7)) << 4);
                ldsm_x4(afr[mi][0], afr[mi][1], afr[mi][2], afr[mi][3], addr);
            }
#pragma unroll
            for (int ni = 0; ni < 4; ni++) {
                uint32_t row = bRow0 + ni * 16;
                uint32_t addr = bB + row * 256 + (((kc) ^ (row & 7)) << 4);
                ldsm_x4(bfr[ni][0], bfr[ni][1], bfr[ni][2], bfr[ni][3], addr);
            }
#pragma unroll
            for (int mi = 0; mi < 2; mi++)
#pragma unroll
                for (int n8 = 0; n8 < 8; n8++) {
                    int ni = n8 >> 1, hh = n8 & 1;
                    mma_bf16(acc[mi][n8][0], acc[mi][n8][1], acc[mi][n8][2], acc[mi][n8][3],
                             afr[mi][0], afr[mi][1], afr[mi][2], afr[mi][3],
                             bfr[ni][hh], bfr[ni][hh + 2]);
                }
        }
    }

    // ---- epilogue: C frag lane l holds (row l/4 [+8], col 2*(l%4)+{0,1}) ----
    int lr4 = lane >> 2, lc2 = (lane & 3) * 2;
#pragma unroll
    for (int mi = 0; mi < 2; mi++) {
#pragma unroll
        for (int hh = 0; hh < 2; hh++) {
            int grow = rowBase + wm * 32 + mi * 16 + hh * 8 + lr4;
            if (grow >= n) continue;
            float ns = g_norm_s[grow];
            float* orow = Hout + (size_t)grow * Nw;
#pragma unroll
            for (int n8 = 0; n8 < 8; n8++) {
                int col = colBase + wn * 64 + n8 * 8 + lc2;
                float sc = (col < Kw) ? ns : 1.0f;
                float2 o;
                o.x = acc[mi][n8][hh * 2 + 0] * sc;
                o.y = acc[mi][n8][hh * 2 + 1] * sc;
                *(float2*)(orow + col) = o;
            }
        }
    }
}

// ---------------- Fused SpMM + combine, Kw=128 (H width 256) ----------------
__global__ void gres_spmm128(const float* __restrict__ bias, float* __restrict__ out, int n,
                             int do_relu) {
    int warp = (blockIdx.x * blockDim.x + threadIdx.x) >> 5;
    if (warp >= n) return;
    int lane = threadIdx.x & 31;
    int row = warp;

    int s0 = g_row_ptr[row];
    int s1 = g_row_ptr[row + 1];

    float4 a0 = make_float4(0.f, 0.f, 0.f, 0.f);
    float4 a1 = make_float4(0.f, 0.f, 0.f, 0.f);

    int j = s0;
    for (; j + 1 < s1; j += 2) {
        int sa = g_csr_src[j];
        int sb = g_csr_src[j + 1];
        const float4* ha = (const float4*)(g_H + (size_t)sa * 256);
        const float4* hb = (const float4*)(g_H + (size_t)sb * 256);
        float4 v0a = ha[lane], v1a = ha[lane + 32];
        float4 v0b = hb[lane], v1b = hb[lane + 32];
        a0.x += v0a.x + v0b.x; a0.y += v0a.y + v0b.y;
        a0.z += v0a.z + v0b.z; a0.w += v0a.w + v0b.w;
        a1.x += v1a.x + v1b.x; a1.y += v1a.y + v1b.y;
        a1.z += v1a.z + v1b.z; a1.w += v1a.w + v1b.w;
    }
    if (j < s1) {
        int sa = g_csr_src[j];
        const float4* ha = (const float4*)(g_H + (size_t)sa * 256);
        float4 v0a = ha[lane], v1a = ha[lane + 32];
        a0.x += v0a.x; a0.y += v0a.y; a0.z += v0a.z; a0.w += v0a.w;
        a1.x += v1a.x; a1.y += v1a.y; a1.z += v1a.z; a1.w += v1a.w;
    }

    float nd = g_norm_d[row];
    float4 b4 = *(const float4*)(bias + lane * 4);
    float4 o;
    o.x = fmaf(a0.x, nd, a1.x + b4.x);
    o.y = fmaf(a0.y, nd, a1.y + b4.y);
    o.z = fmaf(a0.z, nd, a1.z + b4.z);
    o.w = fmaf(a0.w, nd, a1.w + b4.w);
    if (do_relu) {
        o.x = fmaxf(o.x, 0.f); o.y = fmaxf(o.y, 0.f);
        o.z = fmaxf(o.z, 0.f); o.w = fmaxf(o.w, 0.f);
    }
    *(float4*)(out + (size_t)row * 128 + lane * 4) = o;
}

// ---------------- Fused SpMM + combine, Kw=64 (H width 128), no relu ----------------
__global__ void gres_spmm64(const float* __restrict__ bias, float* __restrict__ out, int n) {
    int warp = (blockIdx.x * blockDim.x + threadIdx.x) >> 5;
    if (warp >= n) return;
    int lane = threadIdx.x & 31;
    int row = warp;

    int s0 = g_row_ptr[row];
    int s1 = g_row_ptr[row + 1];

    float4 a0 = make_float4(0.f, 0.f, 0.f, 0.f);

    int j = s0;
    for (; j + 1 < s1; j += 2) {
        int sa = g_csr_src[j];
        int sb = g_csr_src[j + 1];
        const float4* ha = (const float4*)(g_H + (size_t)sa * 128);
        const float4* hb = (const float4*)(g_H + (size_t)sb * 128);
        float4 va = ha[lane], vb = hb[lane];
        a0.x += va.x + vb.x; a0.y += va.y + vb.y;
        a0.z += va.z + vb.z; a0.w += va.w + vb.w;
    }
    if (j < s1) {
        int sa = g_csr_src[j];
        const float4* ha = (const float4*)(g_H + (size_t)sa * 128);
        float4 va = ha[lane];
        a0.x += va.x; a0.y += va.y; a0.z += va.z; a0.w += va.w;
    }

    float ox = __shfl_xor_sync(0xffffffffu, a0.x, 16);
    float oy = __shfl_xor_sync(0xffffffffu, a0.y, 16);
    float oz = __shfl_xor_sync(0xffffffffu, a0.z, 16);
    float ow = __shfl_xor_sync(0xffffffffu, a0.w, 16);

    if (lane < 16) {
        float nd = g_norm_d[row];
        float4 b4 = *(const float4*)(bias + lane * 4);
        float4 o;
        o.x = fmaf(a0.x, nd, ox + b4.x);
        o.y = fmaf(a0.y, nd, oy + b4.y);
        o.z = fmaf(a0.z, nd, oz + b4.z);
        o.w = fmaf(a0.w, nd, ow + b4.w);
        *(float4*)(out + (size_t)row * 64 + lane * 4) = o;
    }
}

// ---------------- Host launch ----------------
extern "C" void kernel_launch(void* const* d_in, const int* in_sizes, int n_in,
                              void* d_out, int out_size) {
    const float* raw_x = (const float*)d_in[0];
    const int*   src   = (const int*)d_in[1];
    const int*   dst   = (const int*)d_in[2];
    const float* gw0   = (const float*)d_in[3];
    const float* gb0   = (const float*)d_in[4];
    const float* gw1   = (const float*)d_in[5];
    const float* gb1   = (const float*)d_in[6];
    const float* gw2   = (const float*)d_in[7];
    const float* gb2   = (const float*)d_in[8];
    const float* rw0   = (const float*)d_in[9];
    const float* rw1   = (const float*)d_in[10];
    const float* rw2   = (const float*)d_in[11];
    float* out = (float*)d_out;

    int n = in_sizes[0] / 128;
    int E = in_sizes[1];

    float* Xp = nullptr;
    float* Hp = nullptr;
    cudaGetSymbolAddress((void**)&Xp, g_X);
    cudaGetSymbolAddress((void**)&Hp, g_H);

    cudaFuncSetAttribute(gres_gemm_mma, cudaFuncAttributeMaxDynamicSharedMemorySize, 131072);

    int nb256 = (n + 255) / 256;

    // graph setup
    gres_zero_deg<<<nb256, 256>>>(n);
    gres_degrees<<<(E + 255) / 256, 256>>>(src, dst, E);
    gres_norms<<<nb256, 256>>>(n);
    gres_scan1<<<nb256, 256>>>(n);
    gres_scan2<<<1, 512>>>(nb256);
    gres_scan3<<<nb256, 256>>>(n);
    gres_scatter<<<(E + 255) / 256, 256>>>(src, dst, E);

    int spmm_blocks = (n + 7) / 8;       // 8 warps / 256-thread block
    int gemm_mblocks = (n + 127) / 128;

    // layer 0: X=raw_x, Kw=128 (Nw=256 -> grid.y=2)
    gres_prep_b<<<128, 256>>>(gw0, rw0, 128);
    gres_gemm_mma<<<dim3(gemm_mblocks, 2), 256, 131072>>>(raw_x, n, 128, Hp);
    gres_spmm128<<<spmm_blocks, 256>>>(gb0, Xp, n, 1);

    // layer 1: X=g_X, Kw=128
    gres_prep_b<<<128, 256>>>(gw1, rw1, 128);
    gres_gemm_mma<<<dim3(gemm_mblocks, 2), 256, 131072>>>(Xp, n, 128, Hp);
    gres_spmm128<<<spmm_blocks, 256>>>(gb1, Xp, n, 1);

    // layer 2: X=g_X, Kw=64 (Nw=128 -> grid.y=1), writes d_out
    gres_prep_b<<<64, 256>>>(gw2, rw2, 64);
    gres_gemm_mma<<<dim3(gemm_mblocks, 1), 256, 131072>>>(Xp, n, 64, Hp);
    gres_spmm64<<<spmm_blocks, 256>>>(gb2, out, n);
}